// round 7
// baseline (speedup 1.0000x reference)
#include <cuda_runtime.h>
#include <cstdint>

// Problem constants
#define NCTA      96     // persistent CTAs (<= 148 SMs, all co-resident)
#define NTHREADS  384    // 12 warps = 3 per SMSP (stall coverage)
#define BB        16     // batch
#define HB        8      // batch half (register-pressure split)
#define TT        1024   // time steps
#define DD        768    // hidden dim
#define NGATES    4
#define DPC       8      // d-columns per CTA (96*8 = 768)
#define GC        32     // gate columns per CTA (interleaved: gc = dl*4 + gate)
#define NSLICE    24     // k-slices = 12 warps x 2 half-warps
#define KS        32     // k per slice (24*32 = 768)
#define KS2       16     // packed f32x2 k-pairs per slice
#define REDHALF   6144   // floats per batch-half spill region (24*256)

// Global exchange state (device globals: no allocation anywhere)
__device__ __align__(16) float    g_hbuf[2][BB * DD];
__device__ unsigned               g_ctr;      // monotonic arrival counter

static __device__ __forceinline__ unsigned long long pack2(float x, float y) {
    unsigned long long r;
    asm("mov.b64 %0, {%1, %2};" : "=l"(r) : "f"(x), "f"(y));
    return r;
}
static __device__ __forceinline__ void fma2(unsigned long long& d,
                                            unsigned long long a,
                                            unsigned long long b) {
    // Packed dual-FMA (Blackwell f32x2) — 2x FFMA throughput vs scalar.
    asm("fma.rn.f32x2 %0, %1, %2, %0;" : "+l"(d) : "l"(a), "l"(b));
}
static __device__ __forceinline__ float2 unpack2(unsigned long long v) {
    float lo, hi;
    asm("mov.b64 {%0, %1}, %2;" : "=f"(lo), "=f"(hi) : "l"(v));
    return make_float2(lo, hi);
}

// Zero the barrier counter before each run (graph replays reuse device globals).
__global__ void rnn_reset_kernel() {
    if (threadIdx.x == 0) g_ctr = 0u;
}

__global__ void __launch_bounds__(NTHREADS, 1)
rnn_persistent_kernel(const float* __restrict__ states,
                      const float* __restrict__ Wx,
                      const float* __restrict__ R,
                      const float* __restrict__ bias,
                      float* __restrict__ out)
{
    // Dynamic smem = 48KB. The spill/reduction scratch ALIASES the h panel in
    // two halves: half-p spills land exactly on h rows p*8..p*8+7, which are
    // dead once pass-p GEMM reads complete (syncthreads-guarded):
    //   red_p layout: smem[p*6144 + sl*256 + b_local*32 + gc]
    extern __shared__ float smem[];
    float* h_sm = smem;                    // [BB][DD] = 12288 floats (GEMM)
    float* red  = smem;                    // 2 x [NSLICE][256]       (reduce)

    const int tid = threadIdx.x;
    const int cta = blockIdx.x;
    const int w   = tid >> 5;        // warp id (0..11)
    const int l   = tid & 31;        // lane
    const int hw  = l >> 4;          // half-warp -> k sub-slice
    const int c   = l & 15;          // column-pair index (0..15)
    const int sl  = (w << 1) | hw;   // k-slice id (0..23)
    const int kb  = sl * KS;         // k base for this slice
    const int gcA = c;               // interleaved gate-col: gg = gc&3, dl = gc>>2
    const int gcB = c + 16;
    const int d0  = cta * DPC;

    // ---- One-time: R slices for BOTH columns into registers (k-pair packed).
    unsigned long long RA[KS2], RB[KS2];   // 64 registers
    {
        const float* RgA = R + (size_t)(gcA & 3) * DD * DD + (size_t)(d0 + (gcA >> 2));
        const float* RgB = R + (size_t)(gcB & 3) * DD * DD + (size_t)(d0 + (gcB >> 2));
        #pragma unroll
        for (int j = 0; j < KS2; ++j) {
            RA[j] = pack2(RgA[(size_t)(kb + 2 * j) * DD],
                          RgA[(size_t)(kb + 2 * j + 1) * DD]);
            RB[j] = pack2(RgB[(size_t)(kb + 2 * j) * DD],
                          RgB[(size_t)(kb + 2 * j + 1) * DD]);
        }
    }

    // ---- One-time: per-cell state (c), biases, and t=0 output row. ----
    float c_state = 0.f, b_i = 0.f, b_f = 0.f, b_z = 0.f, b_o = 0.f;
    int cb = 0, cd = 0;
    if (tid < BB * DPC) {                         // 128 "cell" threads
        cb = tid >> 3;                            // batch
        cd = tid & 7;                             // local d
        const int d = d0 + cd;
        b_i = bias[0 * DD + d];
        b_f = bias[1 * DD + d];
        b_z = bias[2 * DD + d];
        b_o = bias[3 * DD + d];
        const float h0 = states[(size_t)(0 * BB + cb) * DD + d];
        c_state        = states[(size_t)(1 * BB + cb) * DD + d];
        // out layout: [2][B][T+1][NH=1][D]; row t=0 is the initial state.
        out[((size_t)(0 * BB + cb) * (TT + 1) + 0) * DD + d] = h0;
        out[((size_t)(1 * BB + cb) * (TT + 1) + 0) * DD + d] = c_state;
    }

    // ---- Main recurrence ----
    for (int t = 0; t < TT; ++t) {
        // Phase 1: issue Wx(t) loads early (consumed in cell phase).
        float wxi = 0.f, wxf = 0.f, wxz = 0.f, wxo = 0.f;
        if (tid < BB * DPC) {
            const float* wp = Wx + ((size_t)cb * TT + t) * (NGATES * DD) + (d0 + cd);
            wxi = wp[0 * DD];
            wxf = wp[1 * DD];
            wxz = wp[2 * DD];
            wxo = wp[3 * DD];
        }

        // Phase 2: WARP-LOCAL h slice load — warp w needs k in [w*64, w*64+64).
        // 16 float4 x 16 batches per warp; no CTA barrier, __syncwarp suffices.
        {
            const float4* s4 = (const float4*)((t == 0) ? states : g_hbuf[t & 1]);
            float4* d4 = (float4*)h_sm;
            #pragma unroll
            for (int r = 0; r < 8; ++r) {             // 256 float4 per warp
                const int local = r * 32 + l;         // 0..255
                const int b  = local >> 4;            // 16 float4 per batch row
                const int kq = local & 15;
                const int idx = b * (DD / 4) + w * 16 + kq;
                d4[idx] = s4[idx];
            }
            __syncwarp();
        }

        // Phase 3a: GEMM pass 1 — batches 0..7, full 32-k slice.
        unsigned long long accA[HB], accB[HB];        // 32 registers
        #pragma unroll
        for (int b = 0; b < HB; ++b) { accA[b] = 0ull; accB[b] = 0ull; }
        {
            const float* hk = h_sm + kb;              // batch rows 0..7
            #pragma unroll
            for (int j = 0; j < KS2; j += 2) {        // 8 iters, 4 k each
                #pragma unroll
                for (int b = 0; b < HB; ++b) {
                    const ulonglong2 hh =
                        *(const ulonglong2*)(hk + (size_t)b * DD + 2 * j);
                    fma2(accA[b], hh.x, RA[j]);
                    fma2(accA[b], hh.y, RA[j + 1]);
                    fma2(accB[b], hh.x, RB[j]);
                    fma2(accB[b], hh.y, RB[j + 1]);
                }
            }
        }
        __syncthreads();   // S2a: h rows 0..7 dead chip-wide -> spill1 may land

        // Phase 4a: spill pass-1 partials into red half 0 (aliases h rows 0-7).
        {
            float* rw = red + (size_t)sl * 256;
            #pragma unroll
            for (int b = 0; b < HB; ++b) {
                const float2 vA = unpack2(accA[b]);
                const float2 vB = unpack2(accB[b]);
                rw[b * GC + gcA] = vA.x + vA.y;
                rw[b * GC + gcB] = vB.x + vB.y;
            }
        }

        // Phase 3b: GEMM pass 2 — batches 8..15 (reads h rows 8-15 only;
        // disjoint from the spill-1 region, so no sync needed in between).
        #pragma unroll
        for (int b = 0; b < HB; ++b) { accA[b] = 0ull; accB[b] = 0ull; }
        {
            const float* hk = h_sm + (size_t)HB * DD + kb;   // batch rows 8..15
            #pragma unroll
            for (int j = 0; j < KS2; j += 2) {
                #pragma unroll
                for (int b = 0; b < HB; ++b) {
                    const ulonglong2 hh =
                        *(const ulonglong2*)(hk + (size_t)b * DD + 2 * j);
                    fma2(accA[b], hh.x, RA[j]);
                    fma2(accA[b], hh.y, RA[j + 1]);
                    fma2(accB[b], hh.x, RB[j]);
                    fma2(accB[b], hh.y, RB[j + 1]);
                }
            }
        }
        __syncthreads();   // S2b: h rows 8..15 dead chip-wide -> spill2 may land

        // Phase 4b: spill pass-2 partials into red half 1 (aliases h rows 8-15).
        {
            float* rw = red + REDHALF + (size_t)sl * 256;
            #pragma unroll
            for (int b = 0; b < HB; ++b) {
                const float2 vA = unpack2(accA[b]);
                const float2 vB = unpack2(accB[b]);
                rw[b * GC + gcA] = vA.x + vA.y;
                rw[b * GC + gcB] = vB.x + vB.y;
            }
        }
        __syncthreads();   // S3: all partials ready

        // Phase 5+6 fused: cell threads reduce their own 4 gates (one float4
        // per slice, interleaved gc) and run the LSTM update.
        float hn = 0.f, cn = 0.f;
        if (tid < BB * DPC) {
            const int base = (cb >> 3) * REDHALF + (cb & 7) * GC + cd * 4;
            float4 g = make_float4(0.f, 0.f, 0.f, 0.f);
            #pragma unroll
            for (int ss = 0; ss < NSLICE; ++ss) {
                const float4 p = *(const float4*)(red + base + ss * 256);
                g.x += p.x; g.y += p.y; g.z += p.z; g.w += p.w;
            }
            const float gi = g.x + wxi + b_i;
            const float gf = g.y + wxf + b_f;
            const float gz = g.z + wxz + b_z;
            const float go = g.w + wxo + b_o;
            const float i_ = 1.f / (1.f + __expf(-gi));
            const float f_ = 1.f / (1.f + __expf(-gf));
            const float z_ = tanhf(gz);
            const float o_ = 1.f / (1.f + __expf(-go));
            cn = f_ * c_state + i_ * z_;
            hn = o_ * tanhf(cn);
            c_state = cn;
            g_hbuf[(t + 1) & 1][cb * DD + d0 + cd] = hn;  // cross-CTA exchange
        }

        // Phase 7: grid barrier — single monotonic counter, volatile poll
        // (R1/R5-proven; ld.acquire variant measured ~3us/step slower).
        __syncthreads();                   // g_hbuf writes issued by all cells
        if (tid == 0) {
            __threadfence();               // make h writes GPU-visible
            atomicAdd(&g_ctr, 1u);
        }
        // Off-critical-path: out[] rows for step t+1 (never read cross-CTA;
        // overlaps the barrier spin).
        if (tid < BB * DPC) {
            const int d = d0 + cd;
            out[((size_t)(0 * BB + cb) * (TT + 1) + (t + 1)) * DD + d] = hn;
            out[((size_t)(1 * BB + cb) * (TT + 1) + (t + 1)) * DD + d] = cn;
        }
        if (tid == 0) {
            const unsigned target = (unsigned)(NCTA) * (unsigned)(t + 1);
            volatile unsigned* f = &g_ctr;
            while (*f < target) { }
            __threadfence();               // acquire
        }
        __syncthreads();                   // whole CTA may proceed
    }
}

extern "C" void kernel_launch(void* const* d_in, const int* in_sizes, int n_in,
                              void* d_out, int out_size)
{
    const float* states = (const float*)d_in[0];  // [2,16,1,768]
    const float* Wx     = (const float*)d_in[1];  // [16,1024,4,1,768]
    const float* R      = (const float*)d_in[2];  // [4,1,768,768]
    const float* bias   = (const float*)d_in[3];  // [4,1,768]
    float*       out    = (float*)d_out;          // [2,16,1025,1,768]

    const size_t smem_bytes = (size_t)BB * DD * sizeof(float);  // 49152 = 48KB

    rnn_reset_kernel<<<1, 32>>>();
    rnn_persistent_kernel<<<NCTA, NTHREADS, smem_bytes>>>(states, Wx, R, bias, out);
}

// round 8
// speedup vs baseline: 1.2023x; 1.2023x over previous
#include <cuda_runtime.h>
#include <cstdint>

// Problem constants — 2 independent batch groups x 64 CTAs = 128 SMs used
#define NGRP      2
#define GCTAS     64     // CTAs per group (all 128 co-resident on 148 SMs)
#define NCTA      (NGRP * GCTAS)
#define NTHREADS  256    // 8 warps — proven best shape
#define BB        16     // total batch
#define GB        8      // batches per group
#define TT        1024   // time steps
#define DD        768    // hidden dim
#define NGATES    4
#define DPC       12     // d-columns per CTA (64*12 = 768)
#define GC        48     // gate columns per CTA (interleaved: gc = dl*4 + gate)
#define NSLICE    16     // k-slices = 8 warps x 2 half-warps
#define KS        48     // k per slice (16*48 = 768)
#define KS2       24     // packed f32x2 k-pairs per slice
#define REDPITCH  384    // floats per slice spill row (8 b x 48 gc)

// Global exchange state (device globals: no allocation anywhere)
__device__ __align__(16) float    g_hbuf[2][BB * DD];
__device__ unsigned               g_ctr[NGRP * 32];   // 128B-padded per group

static __device__ __forceinline__ unsigned long long pack2(float x, float y) {
    unsigned long long r;
    asm("mov.b64 %0, {%1, %2};" : "=l"(r) : "f"(x), "f"(y));
    return r;
}
static __device__ __forceinline__ void fma2(unsigned long long& d,
                                            unsigned long long a,
                                            unsigned long long b) {
    // Packed dual-FMA (Blackwell f32x2) — 2x FFMA throughput vs scalar.
    asm("fma.rn.f32x2 %0, %1, %2, %0;" : "+l"(d) : "l"(a), "l"(b));
}
static __device__ __forceinline__ float2 unpack2(unsigned long long v) {
    float lo, hi;
    asm("mov.b64 {%0, %1}, %2;" : "=f"(lo), "=f"(hi) : "l"(v));
    return make_float2(lo, hi);
}

// Zero the barrier counters before each run (graph replays reuse device globals).
__global__ void rnn_reset_kernel() {
    if (threadIdx.x < NGRP * 32) g_ctr[threadIdx.x] = 0u;
}

__global__ void __launch_bounds__(NTHREADS, 1)
rnn_persistent_kernel(const float* __restrict__ states,
                      const float* __restrict__ Wx,
                      const float* __restrict__ R,
                      const float* __restrict__ bias,
                      float* __restrict__ out)
{
    // Dynamic smem = 24KB: h panel [GB][DD] = 6144 floats. The spill scratch
    // red [NSLICE][REDPITCH] = 6144 floats ALIASES it (h dead after GEMM,
    // S2-guarded; next-step h load happens only after the group barrier).
    extern __shared__ float smem[];
    float* h_sm = smem;
    float* red  = smem;

    const int tid = threadIdx.x;
    const int grp = blockIdx.x >> 6;     // batch group 0/1
    const int cta = blockIdx.x & 63;     // CTA within group
    const int w   = tid >> 5;            // warp id (0..7)
    const int l   = tid & 31;            // lane
    const int hw  = l >> 4;              // half-warp -> k sub-slice
    const int c   = l & 15;              // column index (0..15)
    const int sl  = (w << 1) | hw;       // k-slice id (0..15)
    const int kb  = sl * KS;             // k base for this slice
    const int gcA = c;                   // 3 interleaved cols: gg = gc&3, dl = gc>>2
    const int gcB = c + 16;
    const int gcC = c + 32;
    const int d0  = cta * DPC;

    // ---- One-time: R slices for all 3 columns into registers (k-pair packed).
    unsigned long long RA[KS2], RB[KS2], RC[KS2];   // 144 registers
    {
        const float* RgA = R + (size_t)(gcA & 3) * DD * DD + (size_t)(d0 + (gcA >> 2));
        const float* RgB = R + (size_t)(gcB & 3) * DD * DD + (size_t)(d0 + (gcB >> 2));
        const float* RgC = R + (size_t)(gcC & 3) * DD * DD + (size_t)(d0 + (gcC >> 2));
        #pragma unroll
        for (int j = 0; j < KS2; ++j) {
            RA[j] = pack2(RgA[(size_t)(kb + 2 * j) * DD], RgA[(size_t)(kb + 2 * j + 1) * DD]);
            RB[j] = pack2(RgB[(size_t)(kb + 2 * j) * DD], RgB[(size_t)(kb + 2 * j + 1) * DD]);
            RC[j] = pack2(RgC[(size_t)(kb + 2 * j) * DD], RgC[(size_t)(kb + 2 * j + 1) * DD]);
        }
    }

    // ---- One-time: per-cell state (c) and t=0 output row. 96 cell threads.
    float c_state = 0.f;
    int gb = 0, cbl = 0, cd = 0;                  // global batch, local batch, local d
    if (tid < GB * DPC) {                         // 96 cells
        cbl = tid / DPC;
        cd  = tid - cbl * DPC;
        gb  = grp * GB + cbl;
        const int d = d0 + cd;
        const float h0 = states[(size_t)(0 * BB + gb) * DD + d];
        c_state        = states[(size_t)(1 * BB + gb) * DD + d];
        out[((size_t)(0 * BB + gb) * (TT + 1) + 0) * DD + d] = h0;
        out[((size_t)(1 * BB + gb) * (TT + 1) + 0) * DD + d] = c_state;
    }

    volatile unsigned* ctr = &g_ctr[grp * 32];

    // ---- Main recurrence ----
    for (int t = 0; t < TT; ++t) {
        // Phase 1: issue Wx(t) + bias loads early (consumed in cell phase;
        // biases loaded per-step to relieve register pressure — L2-resident).
        float wxi = 0.f, wxf = 0.f, wxz = 0.f, wxo = 0.f;
        if (tid < GB * DPC) {
            const int d = d0 + cd;
            const float* wp = Wx + ((size_t)gb * TT + t) * (NGATES * DD) + d;
            wxi = wp[0 * DD] + bias[0 * DD + d];
            wxf = wp[1 * DD] + bias[1 * DD + d];
            wxz = wp[2 * DD] + bias[2 * DD + d];
            wxo = wp[3 * DD] + bias[3 * DD + d];
        }

        // Phase 2: WARP-LOCAL h slice load — warp w needs k in [w*96, w*96+96)
        // for this group's 8 batches. 192 float4 per warp -> 6 per lane.
        {
            const float4* s4 = (const float4*)((t == 0) ? states : g_hbuf[t & 1])
                               + (size_t)grp * GB * (DD / 4);
            float4* d4 = (float4*)h_sm;
            #pragma unroll
            for (int r = 0; r < 6; ++r) {
                const int local = r * 32 + l;          // 0..191
                const int b  = local / 24;             // 24 float4 per k-slice row
                const int kq = local - b * 24;
                const int idx = b * (DD / 4) + w * 24 + kq;
                d4[idx] = s4[idx];
            }
            __syncwarp();
        }

        // Phase 3: GEMM. Half-warp owns 48-k slice; lane owns 3 gate columns.
        // One LDS.128 (4 h, half-warp broadcast) feeds 6 FFMA2.
        unsigned long long accA[GB], accB[GB], accC[GB];   // 48 registers
        #pragma unroll
        for (int b = 0; b < GB; ++b) { accA[b] = 0ull; accB[b] = 0ull; accC[b] = 0ull; }
        {
            const float* hk = h_sm + kb;
            #pragma unroll
            for (int j = 0; j < KS2; j += 2) {        // 12 iters, 4 k each
                #pragma unroll
                for (int b = 0; b < GB; ++b) {
                    const ulonglong2 hh =
                        *(const ulonglong2*)(hk + (size_t)b * DD + 2 * j);
                    fma2(accA[b], hh.x, RA[j]);
                    fma2(accA[b], hh.y, RA[j + 1]);
                    fma2(accB[b], hh.x, RB[j]);
                    fma2(accB[b], hh.y, RB[j + 1]);
                    fma2(accC[b], hh.x, RC[j]);
                    fma2(accC[b], hh.y, RC[j + 1]);
                }
            }
        }
        __syncthreads();   // S2: all warps done reading h_sm (red aliases it!)

        // Phase 4: spill per-slice partials red[sl][b*48+gc] (fold even/odd k).
        {
            float* rw = red + (size_t)sl * REDPITCH;
            #pragma unroll
            for (int b = 0; b < GB; ++b) {
                const float2 vA = unpack2(accA[b]);
                const float2 vB = unpack2(accB[b]);
                const float2 vC = unpack2(accC[b]);
                rw[b * GC + gcA] = vA.x + vA.y;
                rw[b * GC + gcB] = vB.x + vB.y;
                rw[b * GC + gcC] = vC.x + vC.y;
            }
        }
        __syncthreads();   // S3: partials ready

        // Phase 5+6 fused: cell threads reduce their 4 gates (one float4 per
        // slice, interleaved gc) and run the LSTM update.
        float hn = 0.f, cn = 0.f;
        if (tid < GB * DPC) {
            const int off = cbl * GC + cd * 4;        // gates i,f,z,o contiguous
            float4 g = make_float4(0.f, 0.f, 0.f, 0.f);
            #pragma unroll
            for (int ss = 0; ss < NSLICE; ++ss) {
                const float4 p = *(const float4*)(red + ss * REDPITCH + off);
                g.x += p.x; g.y += p.y; g.z += p.z; g.w += p.w;
            }
            const float gi = g.x + wxi;
            const float gf = g.y + wxf;
            const float gz = g.z + wxz;
            const float go = g.w + wxo;
            const float i_ = 1.f / (1.f + __expf(-gi));
            const float f_ = 1.f / (1.f + __expf(-gf));
            const float z_ = tanhf(gz);
            const float o_ = 1.f / (1.f + __expf(-go));
            cn = f_ * c_state + i_ * z_;
            hn = o_ * tanhf(cn);
            c_state = cn;
            g_hbuf[(t + 1) & 1][(size_t)gb * DD + d0 + cd] = hn;   // exchange
        }

        // Phase 7: PER-GROUP grid barrier (64 arrivals) — monotonic counter,
        // volatile poll (R1/R5-proven; acquire-spin measured ~3us/step slower).
        // Groups never synchronize with each other (batches independent).
        __syncthreads();                   // g_hbuf writes issued by all cells
        if (tid == 0) {
            __threadfence();               // make h writes GPU-visible
            atomicAdd((unsigned*)ctr, 1u);
        }
        // Off-critical-path while waiting: out[] rows for t+1 (never read
        // cross-CTA).
        if (tid < GB * DPC) {
            const int d = d0 + cd;
            out[((size_t)(0 * BB + gb) * (TT + 1) + (t + 1)) * DD + d] = hn;
            out[((size_t)(1 * BB + gb) * (TT + 1) + (t + 1)) * DD + d] = cn;
        }
        if (tid == 0) {
            const unsigned target = (unsigned)(GCTAS) * (unsigned)(t + 1);
            while (*ctr < target) { }
            __threadfence();               // acquire
        }
        __syncthreads();                   // whole CTA may proceed
    }
}

extern "C" void kernel_launch(void* const* d_in, const int* in_sizes, int n_in,
                              void* d_out, int out_size)
{
    const float* states = (const float*)d_in[0];  // [2,16,1,768]
    const float* Wx     = (const float*)d_in[1];  // [16,1024,4,1,768]
    const float* R      = (const float*)d_in[2];  // [4,1,768,768]
    const float* bias   = (const float*)d_in[3];  // [4,1,768]
    float*       out    = (float*)d_out;          // [2,16,1025,1,768]

    const size_t smem_bytes = (size_t)GB * DD * sizeof(float);  // 24576 = 24KB

    rnn_reset_kernel<<<1, 64>>>();
    rnn_persistent_kernel<<<NCTA, NTHREADS, smem_bytes>>>(states, Wx, R, bias, out);
}